// round 5
// baseline (speedup 1.0000x reference)
#include <cuda_runtime.h>

// GCN symmetric-normalized CSR aggregation, two-phase:
//   Phase 1: norm_feat[s,:] = rsqrt(deg[s]) * feat[s,:]   (streaming, ~3us)
//   Phase 2: out[d,:] = rsqrt(deg[d]) * sum_{e in row d} norm_feat[col[e],:]
//
// Phase 2: one warp per destination node, lane owns a float2 slice.
// Per 32-edge batch the sources are loaded one-per-lane, then broadcast via
// shfl. Inner loop unrolled x8: 8 independent 256B row gathers in flight
// before any consuming FADD. No per-edge norm loads, no rsqrt, no LDS.

#define FEAT 64
#define FV2  (FEAT / 2)
#define WARPS_PER_BLOCK 8
#define THREADS (WARPS_PER_BLOCK * 32)
#define FULL 0xffffffffu

#define MAX_NODES 100000
__device__ float g_norm_feat[(size_t)MAX_NODES * FEAT];

__global__ __launch_bounds__(256) void scale_feat_kernel(
    const float* __restrict__ node_feat,
    const float* __restrict__ degrees,
    int n_nodes)
{
    const int i = blockIdx.x * blockDim.x + threadIdx.x;   // float4 index
    const int total = n_nodes * (FEAT / 4);
    if (i >= total) return;
    const int node = i >> 4;                               // FEAT/4 = 16 per node
    const float nd = rsqrtf(__ldg(&degrees[node]));
    float4 v = __ldg((const float4*)node_feat + i);
    v.x *= nd; v.y *= nd; v.z *= nd; v.w *= nd;
    ((float4*)g_norm_feat)[i] = v;
}

__global__ __launch_bounds__(THREADS) void gcn_agg_kernel(
    const int* __restrict__ row_ptr,
    const int* __restrict__ col_idx,
    const float* __restrict__ degrees,
    float* __restrict__ out,
    int n_nodes)
{
    const int warp_id = blockIdx.x * WARPS_PER_BLOCK + (threadIdx.x >> 5);
    const int lane = threadIdx.x & 31;
    if (warp_id >= n_nodes) return;

    const int start = __ldg(&row_ptr[warp_id]);
    const int deg   = __ldg(&row_ptr[warp_id + 1]) - start;

    const float2* __restrict__ nf = (const float2*)g_norm_feat;

    float2 a0 = make_float2(0.f, 0.f);
    float2 a1 = make_float2(0.f, 0.f);
    float2 a2 = make_float2(0.f, 0.f);
    float2 a3 = make_float2(0.f, 0.f);

    for (int base = 0; base < deg; base += 32) {
        const int mye = base + lane;
        const int s = (mye < deg) ? __ldg(&col_idx[start + mye]) : 0;
        const int cnt = min(32, deg - base);

        int j = 0;
        for (; j + 8 <= cnt; j += 8) {
            const int s0 = __shfl_sync(FULL, s, j + 0);
            const int s1 = __shfl_sync(FULL, s, j + 1);
            const int s2 = __shfl_sync(FULL, s, j + 2);
            const int s3 = __shfl_sync(FULL, s, j + 3);
            const int s4 = __shfl_sync(FULL, s, j + 4);
            const int s5 = __shfl_sync(FULL, s, j + 5);
            const int s6 = __shfl_sync(FULL, s, j + 6);
            const int s7 = __shfl_sync(FULL, s, j + 7);

            const float2 v0 = __ldg(nf + (size_t)s0 * FV2 + lane);
            const float2 v1 = __ldg(nf + (size_t)s1 * FV2 + lane);
            const float2 v2 = __ldg(nf + (size_t)s2 * FV2 + lane);
            const float2 v3 = __ldg(nf + (size_t)s3 * FV2 + lane);
            const float2 v4 = __ldg(nf + (size_t)s4 * FV2 + lane);
            const float2 v5 = __ldg(nf + (size_t)s5 * FV2 + lane);
            const float2 v6 = __ldg(nf + (size_t)s6 * FV2 + lane);
            const float2 v7 = __ldg(nf + (size_t)s7 * FV2 + lane);

            a0.x += v0.x; a0.y += v0.y;
            a1.x += v1.x; a1.y += v1.y;
            a2.x += v2.x; a2.y += v2.y;
            a3.x += v3.x; a3.y += v3.y;
            a0.x += v4.x; a0.y += v4.y;
            a1.x += v5.x; a1.y += v5.y;
            a2.x += v6.x; a2.y += v6.y;
            a3.x += v7.x; a3.y += v7.y;
        }
        for (; j + 2 <= cnt; j += 2) {
            const int s0 = __shfl_sync(FULL, s, j + 0);
            const int s1 = __shfl_sync(FULL, s, j + 1);
            const float2 v0 = __ldg(nf + (size_t)s0 * FV2 + lane);
            const float2 v1 = __ldg(nf + (size_t)s1 * FV2 + lane);
            a0.x += v0.x; a0.y += v0.y;
            a1.x += v1.x; a1.y += v1.y;
        }
        if (j < cnt) {
            const int s0 = __shfl_sync(FULL, s, j);
            const float2 v0 = __ldg(nf + (size_t)s0 * FV2 + lane);
            a0.x += v0.x; a0.y += v0.y;
        }
    }

    a0.x += a1.x; a0.y += a1.y;
    a2.x += a3.x; a2.y += a3.y;
    a0.x += a2.x; a0.y += a2.y;

    const float nd = rsqrtf(__ldg(&degrees[warp_id]));
    float2 r;
    r.x = a0.x * nd;
    r.y = a0.y * nd;
    ((float2*)out)[(size_t)warp_id * FV2 + lane] = r;
}

// Fallback (no precompute) for n_nodes > MAX_NODES: norm applied per edge.
__global__ __launch_bounds__(THREADS) void gcn_agg_fallback(
    const int* __restrict__ row_ptr,
    const int* __restrict__ col_idx,
    const float* __restrict__ node_feat,
    const float* __restrict__ degrees,
    float* __restrict__ out,
    int n_nodes)
{
    const int warp_id = blockIdx.x * WARPS_PER_BLOCK + (threadIdx.x >> 5);
    const int lane = threadIdx.x & 31;
    if (warp_id >= n_nodes) return;

    const int start = __ldg(&row_ptr[warp_id]);
    const int end   = __ldg(&row_ptr[warp_id + 1]);
    float2 acc = make_float2(0.f, 0.f);
    const float2* nf = (const float2*)node_feat;
    for (int e = start; e < end; ++e) {
        const int s = __ldg(&col_idx[e]);
        const float ns = rsqrtf(__ldg(&degrees[s]));
        const float2 v = __ldg(nf + (size_t)s * FV2 + lane);
        acc.x = fmaf(ns, v.x, acc.x);
        acc.y = fmaf(ns, v.y, acc.y);
    }
    const float nd = rsqrtf(__ldg(&degrees[warp_id]));
    float2 r; r.x = acc.x * nd; r.y = acc.y * nd;
    ((float2*)out)[(size_t)warp_id * FV2 + lane] = r;
}

extern "C" void kernel_launch(void* const* d_in, const int* in_sizes, int n_in,
                              void* d_out, int out_size)
{
    const int*   row_ptr   = (const int*)d_in[0];
    const int*   col_idx   = (const int*)d_in[1];
    const float* node_feat = (const float*)d_in[2];
    const float* degrees   = (const float*)d_in[3];
    float* out = (float*)d_out;

    const int n_nodes = in_sizes[0] - 1;
    const int blocks = (n_nodes + WARPS_PER_BLOCK - 1) / WARPS_PER_BLOCK;

    if (n_nodes <= MAX_NODES) {
        const int total4 = n_nodes * (FEAT / 4);
        scale_feat_kernel<<<(total4 + 255) / 256, 256>>>(node_feat, degrees, n_nodes);
        gcn_agg_kernel<<<blocks, THREADS>>>(row_ptr, col_idx, degrees, out, n_nodes);
    } else {
        gcn_agg_fallback<<<blocks, THREADS>>>(row_ptr, col_idx, node_feat,
                                              degrees, out, n_nodes);
    }
}

// round 6
// speedup vs baseline: 1.4225x; 1.4225x over previous
#include <cuda_runtime.h>
#include <cuda_fp16.h>

// GCN symmetric-normalized CSR aggregation, two-phase:
//   Phase 1: norm_feat[s,:] = (half) rsqrt(deg[s]) * feat[s,:]
//   Phase 2: out[d,:] = rsqrt(deg[d]) * sum_{e in row d} norm_feat[col[e],:]
//
// fp16 gather payload halves L2->L1 traffic (410MB -> 205MB); each edge's
// 64-feat row is one 128B line. Accumulation is fp32 (rel err ~3e-4 << 1e-3).
// Phase 2: one warp per destination node, lane owns a half2 slice. Source
// indices for each 32-edge batch staged in smem, replayed via uniform LDS.

#define FEAT 64
#define WARPS_PER_BLOCK 8
#define THREADS (WARPS_PER_BLOCK * 32)

#define MAX_NODES 100000
__device__ __half g_norm_feat[(size_t)MAX_NODES * FEAT];

__global__ __launch_bounds__(256) void scale_feat_kernel(
    const float* __restrict__ node_feat,
    const float* __restrict__ degrees,
    int n_nodes)
{
    const int i = blockIdx.x * blockDim.x + threadIdx.x;   // float4 index
    const int total = n_nodes * (FEAT / 4);
    if (i >= total) return;
    const int node = i >> 4;                               // 16 float4 per node
    const float nd = rsqrtf(__ldg(&degrees[node]));
    float4 v = __ldg((const float4*)node_feat + i);
    __half2 h0 = __floats2half2_rn(v.x * nd, v.y * nd);
    __half2 h1 = __floats2half2_rn(v.z * nd, v.w * nd);
    __half2* dst = (__half2*)g_norm_feat + (size_t)i * 2;
    dst[0] = h0;
    dst[1] = h1;
}

__global__ __launch_bounds__(THREADS) void gcn_agg_kernel(
    const int* __restrict__ row_ptr,
    const int* __restrict__ col_idx,
    const float* __restrict__ degrees,
    float* __restrict__ out,
    int n_nodes)
{
    __shared__ int sm_src[WARPS_PER_BLOCK][32];

    const int wslot   = threadIdx.x >> 5;
    const int warp_id = blockIdx.x * WARPS_PER_BLOCK + wslot;
    const int lane    = threadIdx.x & 31;
    if (warp_id >= n_nodes) return;

    const int start = __ldg(&row_ptr[warp_id]);
    const int deg   = __ldg(&row_ptr[warp_id + 1]) - start;

    const __half2* __restrict__ nf = (const __half2*)g_norm_feat;

    float2 a0 = make_float2(0.f, 0.f);
    float2 a1 = make_float2(0.f, 0.f);
    float2 a2 = make_float2(0.f, 0.f);
    float2 a3 = make_float2(0.f, 0.f);

    for (int base = 0; base < deg; base += 32) {
        const int mye = base + lane;
        sm_src[wslot][lane] = (mye < deg) ? __ldg(&col_idx[start + mye]) : 0;
        __syncwarp();

        const int cnt = min(32, deg - base);
        int j = 0;
        for (; j + 4 <= cnt; j += 4) {
            const int s0 = sm_src[wslot][j + 0];
            const int s1 = sm_src[wslot][j + 1];
            const int s2 = sm_src[wslot][j + 2];
            const int s3 = sm_src[wslot][j + 3];

            const __half2 h0 = __ldg(nf + (size_t)s0 * (FEAT / 2) + lane);
            const __half2 h1 = __ldg(nf + (size_t)s1 * (FEAT / 2) + lane);
            const __half2 h2 = __ldg(nf + (size_t)s2 * (FEAT / 2) + lane);
            const __half2 h3 = __ldg(nf + (size_t)s3 * (FEAT / 2) + lane);

            const float2 f0 = __half22float2(h0);
            const float2 f1 = __half22float2(h1);
            const float2 f2 = __half22float2(h2);
            const float2 f3 = __half22float2(h3);

            a0.x += f0.x; a0.y += f0.y;
            a1.x += f1.x; a1.y += f1.y;
            a2.x += f2.x; a2.y += f2.y;
            a3.x += f3.x; a3.y += f3.y;
        }
        for (; j < cnt; ++j) {
            const int s = sm_src[wslot][j];
            const float2 f = __half22float2(__ldg(nf + (size_t)s * (FEAT / 2) + lane));
            a0.x += f.x; a0.y += f.y;
        }
        __syncwarp();
    }

    a0.x += a1.x; a0.y += a1.y;
    a2.x += a3.x; a2.y += a3.y;
    a0.x += a2.x; a0.y += a2.y;

    const float nd = rsqrtf(__ldg(&degrees[warp_id]));
    float2 r;
    r.x = a0.x * nd;
    r.y = a0.y * nd;
    ((float2*)out)[(size_t)warp_id * (FEAT / 2) + lane] = r;
}

// Full-precision fallback for n_nodes > MAX_NODES.
__global__ __launch_bounds__(THREADS) void gcn_agg_fallback(
    const int* __restrict__ row_ptr,
    const int* __restrict__ col_idx,
    const float* __restrict__ node_feat,
    const float* __restrict__ degrees,
    float* __restrict__ out,
    int n_nodes)
{
    const int warp_id = blockIdx.x * WARPS_PER_BLOCK + (threadIdx.x >> 5);
    const int lane = threadIdx.x & 31;
    if (warp_id >= n_nodes) return;

    const int start = __ldg(&row_ptr[warp_id]);
    const int end   = __ldg(&row_ptr[warp_id + 1]);
    float2 acc = make_float2(0.f, 0.f);
    const float2* nf = (const float2*)node_feat;
    for (int e = start; e < end; ++e) {
        const int s = __ldg(&col_idx[e]);
        const float ns = rsqrtf(__ldg(&degrees[s]));
        const float2 v = __ldg(nf + (size_t)s * (FEAT / 2) + lane);
        acc.x = fmaf(ns, v.x, acc.x);
        acc.y = fmaf(ns, v.y, acc.y);
    }
    const float nd = rsqrtf(__ldg(&degrees[warp_id]));
    float2 r; r.x = acc.x * nd; r.y = acc.y * nd;
    ((float2*)out)[(size_t)warp_id * (FEAT / 2) + lane] = r;
}

extern "C" void kernel_launch(void* const* d_in, const int* in_sizes, int n_in,
                              void* d_out, int out_size)
{
    const int*   row_ptr   = (const int*)d_in[0];
    const int*   col_idx   = (const int*)d_in[1];
    const float* node_feat = (const float*)d_in[2];
    const float* degrees   = (const float*)d_in[3];
    float* out = (float*)d_out;

    const int n_nodes = in_sizes[0] - 1;
    const int blocks = (n_nodes + WARPS_PER_BLOCK - 1) / WARPS_PER_BLOCK;

    if (n_nodes <= MAX_NODES) {
        const int total4 = n_nodes * (FEAT / 4);
        scale_feat_kernel<<<(total4 + 255) / 256, 256>>>(node_feat, degrees, n_nodes);
        gcn_agg_kernel<<<blocks, THREADS>>>(row_ptr, col_idx, degrees, out, n_nodes);
    } else {
        gcn_agg_fallback<<<blocks, THREADS>>>(row_ptr, col_idx, node_feat,
                                              degrees, out, n_nodes);
    }
}

// round 7
// speedup vs baseline: 1.5659x; 1.1008x over previous
#include <cuda_runtime.h>
#include <cuda_fp16.h>

// GCN symmetric-normalized CSR aggregation, two-phase:
//   Phase 1: norm_feat[s,:] = (half) rsqrt(deg[s]) * feat[s,:]
//   Phase 2: out[d,:] = rsqrt(deg[d]) * sum_{e in row d} norm_feat[col[e],:]
//
// fp16 gather payload: each edge's 64-feat row is one 128B L1 line.
// Phase 2: one warp per destination node, lane owns a half2 slice.
// Source indices for each 32-edge batch staged in smem; inner loop reads
// them back 4-at-a-time with LDS.128 (uniform broadcast) and keeps 8
// independent gathers in flight per iteration. fp32 accumulation.

#define FEAT 64
#define FV2  (FEAT / 2)          // half2 per feature row
#define WARPS_PER_BLOCK 4
#define THREADS (WARPS_PER_BLOCK * 32)

#define MAX_NODES 100000
__device__ __half g_norm_feat[(size_t)MAX_NODES * FEAT];

__global__ __launch_bounds__(256) void scale_feat_kernel(
    const float* __restrict__ node_feat,
    const float* __restrict__ degrees,
    int n_nodes)
{
    const int i = blockIdx.x * blockDim.x + threadIdx.x;   // float4 index
    const int total = n_nodes * (FEAT / 4);
    if (i >= total) return;
    const int node = i >> 4;                               // 16 float4 per node
    const float nd = rsqrtf(__ldg(&degrees[node]));
    float4 v = __ldg((const float4*)node_feat + i);
    __half2 h0 = __floats2half2_rn(v.x * nd, v.y * nd);
    __half2 h1 = __floats2half2_rn(v.z * nd, v.w * nd);
    __half2* dst = (__half2*)g_norm_feat + (size_t)i * 2;
    dst[0] = h0;
    dst[1] = h1;
}

__global__ __launch_bounds__(THREADS) void gcn_agg_kernel(
    const int* __restrict__ row_ptr,
    const int* __restrict__ col_idx,
    const float* __restrict__ degrees,
    float* __restrict__ out,
    int n_nodes)
{
    __shared__ __align__(16) int sm_src[WARPS_PER_BLOCK][32];

    const int wslot   = threadIdx.x >> 5;
    const int warp_id = blockIdx.x * WARPS_PER_BLOCK + wslot;
    const int lane    = threadIdx.x & 31;
    if (warp_id >= n_nodes) return;

    const int start = __ldg(&row_ptr[warp_id]);
    const int deg   = __ldg(&row_ptr[warp_id + 1]) - start;

    const __half2* __restrict__ nf = (const __half2*)g_norm_feat;

    float2 a0 = make_float2(0.f, 0.f);
    float2 a1 = make_float2(0.f, 0.f);
    float2 a2 = make_float2(0.f, 0.f);
    float2 a3 = make_float2(0.f, 0.f);

    for (int base = 0; base < deg; base += 32) {
        const int mye = base + lane;
        sm_src[wslot][lane] = (mye < deg) ? __ldg(&col_idx[start + mye]) : 0;
        __syncwarp();

        const int cnt = min(32, deg - base);
        int j = 0;
        // 8 independent gathers in flight per iteration.
        for (; j + 8 <= cnt; j += 8) {
            const int4 ia = *(const int4*)&sm_src[wslot][j];
            const int4 ib = *(const int4*)&sm_src[wslot][j + 4];

            const __half2 h0 = __ldg(nf + (size_t)ia.x * FV2 + lane);
            const __half2 h1 = __ldg(nf + (size_t)ia.y * FV2 + lane);
            const __half2 h2 = __ldg(nf + (size_t)ia.z * FV2 + lane);
            const __half2 h3 = __ldg(nf + (size_t)ia.w * FV2 + lane);
            const __half2 h4 = __ldg(nf + (size_t)ib.x * FV2 + lane);
            const __half2 h5 = __ldg(nf + (size_t)ib.y * FV2 + lane);
            const __half2 h6 = __ldg(nf + (size_t)ib.z * FV2 + lane);
            const __half2 h7 = __ldg(nf + (size_t)ib.w * FV2 + lane);

            const float2 f0 = __half22float2(h0);
            const float2 f1 = __half22float2(h1);
            const float2 f2 = __half22float2(h2);
            const float2 f3 = __half22float2(h3);
            const float2 f4 = __half22float2(h4);
            const float2 f5 = __half22float2(h5);
            const float2 f6 = __half22float2(h6);
            const float2 f7 = __half22float2(h7);

            a0.x += f0.x; a0.y += f0.y;
            a1.x += f1.x; a1.y += f1.y;
            a2.x += f2.x; a2.y += f2.y;
            a3.x += f3.x; a3.y += f3.y;
            a0.x += f4.x; a0.y += f4.y;
            a1.x += f5.x; a1.y += f5.y;
            a2.x += f6.x; a2.y += f6.y;
            a3.x += f7.x; a3.y += f7.y;
        }
        if (j + 4 <= cnt) {
            const int4 ia = *(const int4*)&sm_src[wslot][j];
            const __half2 h0 = __ldg(nf + (size_t)ia.x * FV2 + lane);
            const __half2 h1 = __ldg(nf + (size_t)ia.y * FV2 + lane);
            const __half2 h2 = __ldg(nf + (size_t)ia.z * FV2 + lane);
            const __half2 h3 = __ldg(nf + (size_t)ia.w * FV2 + lane);
            const float2 f0 = __half22float2(h0);
            const float2 f1 = __half22float2(h1);
            const float2 f2 = __half22float2(h2);
            const float2 f3 = __half22float2(h3);
            a0.x += f0.x; a0.y += f0.y;
            a1.x += f1.x; a1.y += f1.y;
            a2.x += f2.x; a2.y += f2.y;
            a3.x += f3.x; a3.y += f3.y;
            j += 4;
        }
        for (; j < cnt; ++j) {
            const int s = sm_src[wslot][j];
            const float2 f = __half22float2(__ldg(nf + (size_t)s * FV2 + lane));
            a0.x += f.x; a0.y += f.y;
        }
        __syncwarp();
    }

    a0.x += a1.x; a0.y += a1.y;
    a2.x += a3.x; a2.y += a3.y;
    a0.x += a2.x; a0.y += a2.y;

    const float nd = rsqrtf(__ldg(&degrees[warp_id]));
    float2 r;
    r.x = a0.x * nd;
    r.y = a0.y * nd;
    ((float2*)out)[(size_t)warp_id * FV2 + lane] = r;
}

// Full-precision fallback for n_nodes > MAX_NODES.
__global__ __launch_bounds__(THREADS) void gcn_agg_fallback(
    const int* __restrict__ row_ptr,
    const int* __restrict__ col_idx,
    const float* __restrict__ node_feat,
    const float* __restrict__ degrees,
    float* __restrict__ out,
    int n_nodes)
{
    const int warp_id = blockIdx.x * WARPS_PER_BLOCK + (threadIdx.x >> 5);
    const int lane = threadIdx.x & 31;
    if (warp_id >= n_nodes) return;

    const int start = __ldg(&row_ptr[warp_id]);
    const int end   = __ldg(&row_ptr[warp_id + 1]);
    float2 acc = make_float2(0.f, 0.f);
    const float2* nf = (const float2*)node_feat;
    for (int e = start; e < end; ++e) {
        const int s = __ldg(&col_idx[e]);
        const float ns = rsqrtf(__ldg(&degrees[s]));
        const float2 v = __ldg(nf + (size_t)s * FV2 + lane);
        acc.x = fmaf(ns, v.x, acc.x);
        acc.y = fmaf(ns, v.y, acc.y);
    }
    const float nd = rsqrtf(__ldg(&degrees[warp_id]));
    float2 r; r.x = acc.x * nd; r.y = acc.y * nd;
    ((float2*)out)[(size_t)warp_id * FV2 + lane] = r;
}

extern "C" void kernel_launch(void* const* d_in, const int* in_sizes, int n_in,
                              void* d_out, int out_size)
{
    const int*   row_ptr   = (const int*)d_in[0];
    const int*   col_idx   = (const int*)d_in[1];
    const float* node_feat = (const float*)d_in[2];
    const float* degrees   = (const float*)d_in[3];
    float* out = (float*)d_out;

    const int n_nodes = in_sizes[0] - 1;
    const int blocks = (n_nodes + WARPS_PER_BLOCK - 1) / WARPS_PER_BLOCK;

    if (n_nodes <= MAX_NODES) {
        const int total4 = n_nodes * (FEAT / 4);
        scale_feat_kernel<<<(total4 + 255) / 256, 256>>>(node_feat, degrees, n_nodes);
        gcn_agg_kernel<<<blocks, THREADS>>>(row_ptr, col_idx, degrees, out, n_nodes);
    } else {
        gcn_agg_fallback<<<blocks, THREADS>>>(row_ptr, col_idx, node_feat,
                                              degrees, out, n_nodes);
    }
}

// round 8
// speedup vs baseline: 1.6420x; 1.0486x over previous
#include <cuda_runtime.h>
#include <cuda_fp16.h>

// GCN symmetric-normalized CSR aggregation, two-phase:
//   Phase 1: norm_feat[s,:] = (half) rsqrt(deg[s]) * feat[s,:]
//   Phase 2: out[d,:] = rsqrt(deg[d]) * sum_{e in row d} norm_feat[col[e],:]
//
// fp16 gather payload: each edge's 64-feat row is one 128B L1 line.
// One warp per destination node, lane owns a half2 (4B) slice.
// Per 32-edge batch: byte offsets (src*128) staged in smem; inner loop
// fetches 4 offsets per LDS.128, keeps 8 gathers in flight, and folds
// adjacent edges with HADD2 before a single fp32 convert+add per pair.

#define FEAT 64
#define FV2  (FEAT / 2)
#define ROW_BYTES (FEAT * 2)      // 128B per fp16 feature row
#define WARPS_PER_BLOCK 4
#define THREADS (WARPS_PER_BLOCK * 32)

#define MAX_NODES 100000
__device__ __half g_norm_feat[(size_t)MAX_NODES * FEAT];

__global__ __launch_bounds__(256) void scale_feat_kernel(
    const float* __restrict__ node_feat,
    const float* __restrict__ degrees,
    int n_nodes)
{
    const int i = blockIdx.x * blockDim.x + threadIdx.x;   // float4 index
    const int total = n_nodes * (FEAT / 4);
    if (i >= total) return;
    const int node = i >> 4;                               // 16 float4 per node
    const float nd = rsqrtf(__ldg(&degrees[node]));
    float4 v = __ldg((const float4*)node_feat + i);
    __half2 h0 = __floats2half2_rn(v.x * nd, v.y * nd);
    __half2 h1 = __floats2half2_rn(v.z * nd, v.w * nd);
    __half2* dst = (__half2*)g_norm_feat + (size_t)i * 2;
    dst[0] = h0;
    dst[1] = h1;
}

__global__ __launch_bounds__(THREADS) void gcn_agg_kernel(
    const int* __restrict__ row_ptr,
    const int* __restrict__ col_idx,
    const float* __restrict__ degrees,
    float* __restrict__ out,
    int n_nodes)
{
    __shared__ __align__(16) unsigned sm_off[WARPS_PER_BLOCK][32];

    const int wslot   = threadIdx.x >> 5;
    const int warp_id = blockIdx.x * WARPS_PER_BLOCK + wslot;
    const int lane    = threadIdx.x & 31;
    if (warp_id >= n_nodes) return;

    const int start = __ldg(&row_ptr[warp_id]);
    const int deg   = __ldg(&row_ptr[warp_id + 1]) - start;

    // Per-lane base pointer into the fp16 table (lane's 4B slice of a row).
    const char* __restrict__ base = (const char*)g_norm_feat + (size_t)lane * 4;

    float2 a0 = make_float2(0.f, 0.f);
    float2 a1 = make_float2(0.f, 0.f);
    float2 a2 = make_float2(0.f, 0.f);
    float2 a3 = make_float2(0.f, 0.f);

    for (int bbase = 0; bbase < deg; bbase += 32) {
        const int mye = bbase + lane;
        const int s = (mye < deg) ? __ldg(&col_idx[start + mye]) : 0;
        sm_off[wslot][lane] = (unsigned)s * ROW_BYTES;   // pre-multiplied byte offset
        __syncwarp();

        const int cnt = min(32, deg - bbase);
        int j = 0;
        for (; j + 8 <= cnt; j += 8) {
            const uint4 ia = *(const uint4*)&sm_off[wslot][j];
            const uint4 ib = *(const uint4*)&sm_off[wslot][j + 4];

            const __half2 h0 = __ldg((const __half2*)(base + ia.x));
            const __half2 h1 = __ldg((const __half2*)(base + ia.y));
            const __half2 h2 = __ldg((const __half2*)(base + ia.z));
            const __half2 h3 = __ldg((const __half2*)(base + ia.w));
            const __half2 h4 = __ldg((const __half2*)(base + ib.x));
            const __half2 h5 = __ldg((const __half2*)(base + ib.y));
            const __half2 h6 = __ldg((const __half2*)(base + ib.z));
            const __half2 h7 = __ldg((const __half2*)(base + ib.w));

            // Fold adjacent edges in fp16 (one rounding per pair), then fp32.
            const float2 p0 = __half22float2(__hadd2(h0, h1));
            const float2 p1 = __half22float2(__hadd2(h2, h3));
            const float2 p2 = __half22float2(__hadd2(h4, h5));
            const float2 p3 = __half22float2(__hadd2(h6, h7));

            a0.x += p0.x; a0.y += p0.y;
            a1.x += p1.x; a1.y += p1.y;
            a2.x += p2.x; a2.y += p2.y;
            a3.x += p3.x; a3.y += p3.y;
        }
        if (j + 4 <= cnt) {
            const uint4 ia = *(const uint4*)&sm_off[wslot][j];
            const __half2 h0 = __ldg((const __half2*)(base + ia.x));
            const __half2 h1 = __ldg((const __half2*)(base + ia.y));
            const __half2 h2 = __ldg((const __half2*)(base + ia.z));
            const __half2 h3 = __ldg((const __half2*)(base + ia.w));
            const float2 p0 = __half22float2(__hadd2(h0, h1));
            const float2 p1 = __half22float2(__hadd2(h2, h3));
            a0.x += p0.x; a0.y += p0.y;
            a1.x += p1.x; a1.y += p1.y;
            j += 4;
        }
        for (; j < cnt; ++j) {
            const unsigned off = sm_off[wslot][j];
            const float2 f = __half22float2(__ldg((const __half2*)(base + off)));
            a2.x += f.x; a2.y += f.y;
        }
        __syncwarp();
    }

    a0.x += a1.x; a0.y += a1.y;
    a2.x += a3.x; a2.y += a3.y;
    a0.x += a2.x; a0.y += a2.y;

    const float nd = rsqrtf(__ldg(&degrees[warp_id]));
    float2 r;
    r.x = a0.x * nd;
    r.y = a0.y * nd;
    ((float2*)out)[(size_t)warp_id * FV2 + lane] = r;
}

// Full-precision fallback for n_nodes > MAX_NODES.
__global__ __launch_bounds__(THREADS) void gcn_agg_fallback(
    const int* __restrict__ row_ptr,
    const int* __restrict__ col_idx,
    const float* __restrict__ node_feat,
    const float* __restrict__ degrees,
    float* __restrict__ out,
    int n_nodes)
{
    const int warp_id = blockIdx.x * WARPS_PER_BLOCK + (threadIdx.x >> 5);
    const int lane = threadIdx.x & 31;
    if (warp_id >= n_nodes) return;

    const int start = __ldg(&row_ptr[warp_id]);
    const int end   = __ldg(&row_ptr[warp_id + 1]);
    float2 acc = make_float2(0.f, 0.f);
    const float2* nf = (const float2*)node_feat;
    for (int e = start; e < end; ++e) {
        const int s = __ldg(&col_idx[e]);
        const float ns = rsqrtf(__ldg(&degrees[s]));
        const float2 v = __ldg(nf + (size_t)s * FV2 + lane);
        acc.x = fmaf(ns, v.x, acc.x);
        acc.y = fmaf(ns, v.y, acc.y);
    }
    const float nd = rsqrtf(__ldg(&degrees[warp_id]));
    float2 r; r.x = acc.x * nd; r.y = acc.y * nd;
    ((float2*)out)[(size_t)warp_id * FV2 + lane] = r;
}

extern "C" void kernel_launch(void* const* d_in, const int* in_sizes, int n_in,
                              void* d_out, int out_size)
{
    const int*   row_ptr   = (const int*)d_in[0];
    const int*   col_idx   = (const int*)d_in[1];
    const float* node_feat = (const float*)d_in[2];
    const float* degrees   = (const float*)d_in[3];
    float* out = (float*)d_out;

    const int n_nodes = in_sizes[0] - 1;
    const int blocks = (n_nodes + WARPS_PER_BLOCK - 1) / WARPS_PER_BLOCK;

    if (n_nodes <= MAX_NODES) {
        const int total4 = n_nodes * (FEAT / 4);
        scale_feat_kernel<<<(total4 + 255) / 256, 256>>>(node_feat, degrees, n_nodes);
        gcn_agg_kernel<<<blocks, THREADS>>>(row_ptr, col_idx, degrees, out, n_nodes);
    } else {
        gcn_agg_fallback<<<blocks, THREADS>>>(row_ptr, col_idx, node_feat,
                                              degrees, out, n_nodes);
    }
}

// round 9
// speedup vs baseline: 1.7457x; 1.0632x over previous
#include <cuda_runtime.h>
#include <cuda_fp16.h>

// GCN symmetric-normalized CSR aggregation, two-phase:
//   Phase 1: norm_feat[s,:] = (half) rsqrt(deg[s]) * feat[s,:]; plus a
//            guaranteed all-zero row at index MAX_NODES (padding target).
//   Phase 2: out[d,:] = rsqrt(deg[d]) * sum_{e in row d} norm_feat[col[e],:]
//
// Phase 2: one warp per destination node. 16 lanes cover a 128B fp16 row
// (8B per lane), so each LDG.64 gathers TWO edges (one per half-warp).
// Offsets staged deinterleaved in smem (half h reads slots [16h,16h+16) via
// LDS.128); invalid slots point at the zero row -> branch-free inner loop.
// Four edges per half folded with a 2-level HADD2 tree, then fp32 accumulate.

#define FEAT 64
#define ROW_BYTES (FEAT * 2)     // 128B per fp16 feature row
#define WARPS_PER_BLOCK 4
#define THREADS (WARPS_PER_BLOCK * 32)
#define FULL 0xffffffffu

#define MAX_NODES 100000
// +1 row of zeros used as the padding gather target.
__device__ __half g_norm_feat[(size_t)(MAX_NODES + 1) * FEAT];

__global__ __launch_bounds__(256) void scale_feat_kernel(
    const float* __restrict__ node_feat,
    const float* __restrict__ degrees,
    int n_nodes)
{
    const int i = blockIdx.x * blockDim.x + threadIdx.x;   // float4 index
    const int total = (n_nodes + 1) * (FEAT / 4);          // +1: zero row
    if (i >= total) return;
    const int node = i >> 4;                               // 16 float4 per node
    __half2 h0, h1;
    if (node < n_nodes) {
        const float nd = rsqrtf(__ldg(&degrees[node]));
        float4 v = __ldg((const float4*)node_feat + i);
        h0 = __floats2half2_rn(v.x * nd, v.y * nd);
        h1 = __floats2half2_rn(v.z * nd, v.w * nd);
    } else {
        h0 = __floats2half2_rn(0.f, 0.f);
        h1 = h0;
    }
    __half2* dst = (__half2*)g_norm_feat + (size_t)i * 2;
    dst[0] = h0;
    dst[1] = h1;
}

__global__ __launch_bounds__(THREADS) void gcn_agg_kernel(
    const int* __restrict__ row_ptr,
    const int* __restrict__ col_idx,
    const float* __restrict__ degrees,
    float* __restrict__ out,
    int n_nodes)
{
    __shared__ __align__(16) unsigned sm_off[WARPS_PER_BLOCK][32];

    const int wslot   = threadIdx.x >> 5;
    const int warp_id = blockIdx.x * WARPS_PER_BLOCK + wslot;
    const int lane    = threadIdx.x & 31;
    if (warp_id >= n_nodes) return;

    const int half = lane >> 4;          // which edge of the pair
    const int fl   = lane & 15;          // 8B slot within the 128B row

    const int start = __ldg(&row_ptr[warp_id]);
    const int deg   = __ldg(&row_ptr[warp_id + 1]) - start;

    // Per-lane base pointer: this lane's 8B slice of any row.
    const char* __restrict__ base = (const char*)g_norm_feat + (size_t)fl * 8;
    const unsigned ZOFF = (unsigned)MAX_NODES * ROW_BYTES;   // zero-row offset

    float2 a0 = make_float2(0.f, 0.f);   // lane's first half2 slot (fp32)
    float2 a1 = make_float2(0.f, 0.f);   // lane's second half2 slot (fp32)

    const unsigned* __restrict__ myoff = &sm_off[wslot][half << 4];

    for (int bbase = 0; bbase < deg; bbase += 32) {
        // Stage up to 32 offsets, deinterleaved: edge (bbase+lane) goes to
        // slot (lane&1)*16 + lane/2 so half h reads sequential slots.
        const int mye = bbase + lane;
        unsigned off = ZOFF;
        if (mye < deg) off = (unsigned)__ldg(&col_idx[start + mye]) * ROW_BYTES;
        sm_off[wslot][((lane & 1) << 4) | (lane >> 1)] = off;
        __syncwarp();

        const int cnt = min(32, deg - bbase);
        const int c0 = (cnt + 1) >> 1;            // edges handled by half 0 (>= half 1)
        const int iters = (c0 + 3) >> 2;          // 4 edges per half per iteration

        for (int it = 0; it < iters; ++it) {
            const uint4 o = *(const uint4*)(myoff + (it << 2));

            const uint2 d0 = __ldg((const uint2*)(base + o.x));
            const uint2 d1 = __ldg((const uint2*)(base + o.y));
            const uint2 d2 = __ldg((const uint2*)(base + o.z));
            const uint2 d3 = __ldg((const uint2*)(base + o.w));

            // 2-level fp16 tree over the 4 edges, per half2 slot.
            const __half2 t0 = __hadd2(*(const __half2*)&d0.x, *(const __half2*)&d1.x);
            const __half2 t1 = __hadd2(*(const __half2*)&d2.x, *(const __half2*)&d3.x);
            const __half2 u0 = __hadd2(t0, t1);

            const __half2 s0 = __hadd2(*(const __half2*)&d0.y, *(const __half2*)&d1.y);
            const __half2 s1 = __hadd2(*(const __half2*)&d2.y, *(const __half2*)&d3.y);
            const __half2 u1 = __hadd2(s0, s1);

            const float2 f0 = __half22float2(u0);
            const float2 f1 = __half22float2(u1);
            a0.x += f0.x; a0.y += f0.y;
            a1.x += f1.x; a1.y += f1.y;
        }
        __syncwarp();
    }

    // Fold the two halves together (lanes with equal fl share feature slots).
    a0.x += __shfl_xor_sync(FULL, a0.x, 16);
    a0.y += __shfl_xor_sync(FULL, a0.y, 16);
    a1.x += __shfl_xor_sync(FULL, a1.x, 16);
    a1.y += __shfl_xor_sync(FULL, a1.y, 16);

    if (half == 0) {
        const float nd = rsqrtf(__ldg(&degrees[warp_id]));
        float4 r;
        r.x = a0.x * nd;
        r.y = a0.y * nd;
        r.z = a1.x * nd;
        r.w = a1.y * nd;
        ((float4*)out)[(size_t)warp_id * (FEAT / 4) + fl] = r;
    }
}

// Full-precision fallback for n_nodes > MAX_NODES.
__global__ __launch_bounds__(THREADS) void gcn_agg_fallback(
    const int* __restrict__ row_ptr,
    const int* __restrict__ col_idx,
    const float* __restrict__ node_feat,
    const float* __restrict__ degrees,
    float* __restrict__ out,
    int n_nodes)
{
    const int warp_id = blockIdx.x * WARPS_PER_BLOCK + (threadIdx.x >> 5);
    const int lane = threadIdx.x & 31;
    if (warp_id >= n_nodes) return;

    const int start = __ldg(&row_ptr[warp_id]);
    const int end   = __ldg(&row_ptr[warp_id + 1]);
    float2 acc = make_float2(0.f, 0.f);
    const float2* nf = (const float2*)node_feat;
    for (int e = start; e < end; ++e) {
        const int s = __ldg(&col_idx[e]);
        const float ns = rsqrtf(__ldg(&degrees[s]));
        const float2 v = __ldg(nf + (size_t)s * (FEAT / 2) + lane);
        acc.x = fmaf(ns, v.x, acc.x);
        acc.y = fmaf(ns, v.y, acc.y);
    }
    const float nd = rsqrtf(__ldg(&degrees[warp_id]));
    float2 r; r.x = acc.x * nd; r.y = acc.y * nd;
    ((float2*)out)[(size_t)warp_id * (FEAT / 2) + lane] = r;
}

extern "C" void kernel_launch(void* const* d_in, const int* in_sizes, int n_in,
                              void* d_out, int out_size)
{
    const int*   row_ptr   = (const int*)d_in[0];
    const int*   col_idx   = (const int*)d_in[1];
    const float* node_feat = (const float*)d_in[2];
    const float* degrees   = (const float*)d_in[3];
    float* out = (float*)d_out;

    const int n_nodes = in_sizes[0] - 1;
    const int blocks = (n_nodes + WARPS_PER_BLOCK - 1) / WARPS_PER_BLOCK;

    if (n_nodes <= MAX_NODES) {
        const int total4 = (n_nodes + 1) * (FEAT / 4);
        scale_feat_kernel<<<(total4 + 255) / 256, 256>>>(node_feat, degrees, n_nodes);
        gcn_agg_kernel<<<blocks, THREADS>>>(row_ptr, col_idx, degrees, out, n_nodes);
    } else {
        gcn_agg_fallback<<<blocks, THREADS>>>(row_ptr, col_idx, node_feat,
                                              degrees, out, n_nodes);
    }
}